// round 4
// baseline (speedup 1.0000x reference)
#include <cuda_runtime.h>
#include <stdint.h>

#define N_  5000
#define D_  128
#define T_  100
#define K_  20
#define NN_ 40      // n per block
#define EPSV 1e-8f

#define PI_OFF    0
#define THETA_OFF 64000000   // N*D*T
#define PHIP_OFF  74000000   // + N*K*T

// Flag: 1 if event_times buffer is int64, 0 if int32. Written by detect kernel.
__device__ int g_ev64_flag;

// fast exp2-based exp: rel err ~2e-8 for the small |x| seen here (0.1*N(0,1))
__device__ __forceinline__ float fexp(float x) {
    float y = x * 1.4426950408889634f;       // x * log2(e)
    float t = y + 12582912.0f;               // round-to-nearest-int trick
    int   e = __float_as_int(t) << 23;       // n << 23
    float n = t - 12582912.0f;
    float f = y - n;                         // f in [-0.5, 0.5]
    float p = 0.00133335581f;
    p = fmaf(p, f, 0.00961812910f);
    p = fmaf(p, f, 0.0555041086f);
    p = fmaf(p, f, 0.240226512f);
    p = fmaf(p, f, 0.693147182f);
    p = fmaf(p, f, 1.0f);
    return __int_as_float(__float_as_int(p) + e);
}

// ---------------- Kernel 0: detect event_times dtype ----------------
// Values are in [0,100). If the buffer is int64 (little-endian), every odd
// int32 word is a high word == 0. If int32, odd words are samples, each ==0
// with prob 1/100; P(all 32 zero | int32) = 1e-64. Deterministic per input.
__global__ void detect_ev_kernel(const int* __restrict__ ev32) {
    int v = ev32[2 * threadIdx.x + 1];            // odd words 1,3,...,63
    unsigned any = __ballot_sync(0xffffffffu, v != 0);
    if (threadIdx.x == 0) g_ev64_flag = (any == 0) ? 1 : 0;
}

// ---------------- Kernel 1: phi_prob = sigmoid(phi) ----------------
__global__ void phi_sigmoid_kernel(const float* __restrict__ phi,
                                   float* __restrict__ phiP) {
    int i = blockIdx.x * blockDim.x + threadIdx.x;   // 64000 float4s
    float4 v = ((const float4*)phi)[i];
    v.x = 1.0f / (1.0f + fexp(-v.x));
    v.y = 1.0f / (1.0f + fexp(-v.y));
    v.z = 1.0f / (1.0f + fexp(-v.z));
    v.w = 1.0f / (1.0f + fexp(-v.w));
    ((float4*)phiP)[i] = v;
}

// ---------------- Kernel 2: fused softmax + mixture + mask + clip ----------------
// Block: one t8 window [t0, t0+8) (two 4t chunks A/B, B predicated off in the
// tail block t0=96) x 40 n's. 512 threads = 16 warps.
// Warp w: d-slices {(w&1)*64 + lane, +32}, n-range (w>>1)*5 .. +4.
// Shared (107520B): phiP A/B tiles [K][D] float4 + theta A/B tiles [NN][K] float4.
// Same thread writes both 16B halves of each 32B pi/theta sector -> guaranteed
// L2 write merge (no DRAM write amplification).
__global__ __launch_bounds__(512, 1)
void mixture_kernel(const float* __restrict__ lambda_,
                    const int*   __restrict__ ev32,   // raw words of event_times
                    const float* __restrict__ phiP,
                    float* __restrict__ pi,
                    float* __restrict__ theta_out) {
    extern __shared__ float sh[];
    float* phiA_sh = sh;                           // 20*128*4 floats
    float* phiB_sh = phiA_sh + K_ * D_ * 4;
    float* thA_sh  = phiB_sh + K_ * D_ * 4;        // 40*20*4 floats
    float* thB_sh  = thA_sh + NN_ * K_ * 4;

    const int t0   = blockIdx.x * 8;
    const int n0   = blockIdx.y * NN_;
    const int tid  = threadIdx.x;
    const bool has2 = (t0 + 4 < T_);               // tail block: chunk B off
    const int is64 = g_ev64_flag;                  // uniform across grid

    // ---- cooperative load of phiP tiles: 2x2560 float4 ----
#pragma unroll
    for (int i = 0; i < 5; i++) {
        int idx = tid + i * 512;                   // 0..2559
        int k = idx >> 7;
        int d = idx & 127;
        const float* src = phiP + (k * D_ + d) * T_ + t0;
        ((float4*)phiA_sh)[k * D_ + d] = *(const float4*)src;
        if (has2)
            ((float4*)phiB_sh)[k * D_ + d] = *(const float4*)(src + 4);
    }

    // ---- softmax over K for (40 n) x (8 t): 320 tasks ----
    if (tid < NN_ * 8) {
        int nl = tid >> 3;
        int tl = tid & 7;
        if (tl < 4 || has2) {
            const float* lp = lambda_ + ((size_t)(n0 + nl) * K_) * T_ + t0 + tl;
            float e[K_];
            float s = 0.0f;
#pragma unroll
            for (int k = 0; k < K_; k++) {
                e[k] = fexp(lp[k * T_]);
                s += e[k];
            }
            float inv = 1.0f / s;
            float* dst = (tl < 4 ? thA_sh : thB_sh) + (tl & 3);
#pragma unroll
            for (int k = 0; k < K_; k++)
                dst[(nl * K_ + k) * 4] = e[k] * inv;
        }
    }
    __syncthreads();

    // ---- write theta tiles to global (both halves of each 32B sector) ----
    for (int i = tid; i < NN_ * K_; i += 512) {
        int nl = i / K_;
        int k  = i % K_;
        float* dst = theta_out + ((size_t)(n0 + nl) * K_ + k) * T_ + t0;
        *(float4*)dst = ((float4*)thA_sh)[i];
        if (has2)
            *(float4*)(dst + 4) = ((float4*)thB_sh)[i];
    }

    // ---- main register-tiled mixture: 2 d-slices x 5 n per warp ----
    const int w    = tid >> 5;
    const int lane = tid & 31;
    const int d0   = (w & 1) * 64 + lane;          // first d-slice
    const int d1   = d0 + 32;                      // second d-slice
    const int nl0  = (w >> 1) * 5;                 // 8 groups x 5 = 40 n

    // prefetch event times: element idx -> int32 word (idx << is64) reads the
    // low word for int64 buffers (values in [0,100), high word always 0) and
    // the value itself for int32 buffers.
    int etA[5], etB[5];
#pragma unroll
    for (int j = 0; j < 5; j++) {
        size_t iA = (size_t)(n0 + nl0 + j) * D_ + d0;
        size_t iB = (size_t)(n0 + nl0 + j) * D_ + d1;
        etA[j] = ev32[iA << is64];
        etB[j] = ev32[iB << is64];
    }

    const float hi = 1.0f - EPSV;

    // two sequential chunks (B skipped in tail block), same accumulator regs
#pragma unroll
    for (int c = 0; c < 2; c++) {
        if (c == 1 && !has2) break;
        const float* phic = (c == 0) ? phiA_sh : phiB_sh;
        const float* thc  = (c == 0) ? thA_sh  : thB_sh;
        const int tc = t0 + c * 4;

        unsigned long long aA0[5], aA1[5], aB0[5], aB1[5];
#pragma unroll
        for (int j = 0; j < 5; j++) { aA0[j]=0ull; aA1[j]=0ull; aB0[j]=0ull; aB1[j]=0ull; }

        const ulonglong2* thv = (const ulonglong2*)thc;
        const ulonglong2* pv  = (const ulonglong2*)phic;

#pragma unroll
        for (int k = 0; k < K_; k++) {
            ulonglong2 pA = pv[k * D_ + d0];       // lane-distinct, conflict-free LDS.128
            ulonglong2 pB = pv[k * D_ + d1];
#pragma unroll
            for (int j = 0; j < 5; j++) {
                ulonglong2 th = thv[(nl0 + j) * K_ + k];   // warp-broadcast LDS.128
                asm("fma.rn.f32x2 %0, %1, %2, %0;" : "+l"(aA0[j]) : "l"(th.x), "l"(pA.x));
                asm("fma.rn.f32x2 %0, %1, %2, %0;" : "+l"(aA1[j]) : "l"(th.y), "l"(pA.y));
                asm("fma.rn.f32x2 %0, %1, %2, %0;" : "+l"(aB0[j]) : "l"(th.x), "l"(pB.x));
                asm("fma.rn.f32x2 %0, %1, %2, %0;" : "+l"(aB1[j]) : "l"(th.y), "l"(pB.y));
            }
        }

        // ---- mask + clip + store ----
#pragma unroll
        for (int j = 0; j < 5; j++) {
            float x0, x1, x2, x3;
            int e; float4 r;

            asm("mov.b64 {%0,%1}, %2;" : "=f"(x0), "=f"(x1) : "l"(aA0[j]));
            asm("mov.b64 {%0,%1}, %2;" : "=f"(x2), "=f"(x3) : "l"(aA1[j]));
            e = etA[j];
            r.x = (tc + 0 <= e) ? fminf(fmaxf(x0, EPSV), hi) : EPSV;
            r.y = (tc + 1 <= e) ? fminf(fmaxf(x1, EPSV), hi) : EPSV;
            r.z = (tc + 2 <= e) ? fminf(fmaxf(x2, EPSV), hi) : EPSV;
            r.w = (tc + 3 <= e) ? fminf(fmaxf(x3, EPSV), hi) : EPSV;
            *(float4*)(pi + ((size_t)(n0 + nl0 + j) * D_ + d0) * T_ + tc) = r;

            asm("mov.b64 {%0,%1}, %2;" : "=f"(x0), "=f"(x1) : "l"(aB0[j]));
            asm("mov.b64 {%0,%1}, %2;" : "=f"(x2), "=f"(x3) : "l"(aB1[j]));
            e = etB[j];
            r.x = (tc + 0 <= e) ? fminf(fmaxf(x0, EPSV), hi) : EPSV;
            r.y = (tc + 1 <= e) ? fminf(fmaxf(x1, EPSV), hi) : EPSV;
            r.z = (tc + 2 <= e) ? fminf(fmaxf(x2, EPSV), hi) : EPSV;
            r.w = (tc + 3 <= e) ? fminf(fmaxf(x3, EPSV), hi) : EPSV;
            *(float4*)(pi + ((size_t)(n0 + nl0 + j) * D_ + d1) * T_ + tc) = r;
        }
    }
}

extern "C" void kernel_launch(void* const* d_in, const int* in_sizes, int n_in,
                              void* d_out, int out_size) {
    const float* lambda_ = (const float*)d_in[0];   // [N,K,T] f32
    const float* phi     = (const float*)d_in[1];   // [K,D,T] f32
    const int*   ev32    = (const int*)d_in[2];     // [N,D] int32 OR int64 (detected)

    float* out    = (float*)d_out;
    float* pi     = out + PI_OFF;
    float* theta  = out + THETA_OFF;
    float* phiP   = out + PHIP_OFF;

    const int smem = 2 * (K_ * D_ * 4 + NN_ * K_ * 4) * (int)sizeof(float); // 107520
    cudaFuncSetAttribute(mixture_kernel,
                         cudaFuncAttributeMaxDynamicSharedMemorySize, smem);

    // K0: detect event_times dtype (writes g_ev64_flag)
    detect_ev_kernel<<<1, 32>>>(ev32);

    // K1: phi_prob = sigmoid(phi): 256000 elems = 64000 float4
    phi_sigmoid_kernel<<<250, 256>>>(phi, phiP);

    // K2: fused softmax + mixture. grid: x = t8 windows (13, last = 4t tail),
    // y = n-tiles (125)
    dim3 grid((T_ + 7) / 8, N_ / NN_);
    mixture_kernel<<<grid, 512, smem>>>(lambda_, ev32, phiP, pi, theta);
}

// round 12
// speedup vs baseline: 1.0109x; 1.0109x over previous
#include <cuda_runtime.h>
#include <stdint.h>

#define N_  5000
#define D_  128
#define T_  100
#define K_  20
#define NN_ 20      // n per block
#define EPSV 1e-8f

#define PI_OFF    0
#define THETA_OFF 64000000   // N*D*T
#define PHIP_OFF  74000000   // + N*K*T

// fast exp2-based exp: rel err ~2e-8 for the small |x| seen here (0.1*N(0,1))
__device__ __forceinline__ float fexp(float x) {
    float y = x * 1.4426950408889634f;       // x * log2(e)
    float t = y + 12582912.0f;               // round-to-nearest-int trick
    int   e = __float_as_int(t) << 23;       // n << 23
    float n = t - 12582912.0f;
    float f = y - n;                         // f in [-0.5, 0.5]
    float p = 0.00133335581f;
    p = fmaf(p, f, 0.00961812910f);
    p = fmaf(p, f, 0.0555041086f);
    p = fmaf(p, f, 0.240226512f);
    p = fmaf(p, f, 0.693147182f);
    p = fmaf(p, f, 1.0f);
    return __int_as_float(__float_as_int(p) + e);
}

// ---------------- Kernel 1: phi_prob = sigmoid(phi) ----------------
__global__ void phi_sigmoid_kernel(const float* __restrict__ phi,
                                   float* __restrict__ phiP) {
    int i = blockIdx.x * blockDim.x + threadIdx.x;   // 64000 float4s
    float4 v = ((const float4*)phi)[i];
    v.x = 1.0f / (1.0f + fexp(-v.x));
    v.y = 1.0f / (1.0f + fexp(-v.y));
    v.z = 1.0f / (1.0f + fexp(-v.z));
    v.w = 1.0f / (1.0f + fexp(-v.w));
    ((float4*)phiP)[i] = v;
}

// ---------------- Kernel 2: fused softmax + mixture + mask + clip ----------------
// Block: one t8 window [t0,t0+8) (two 4t chunks A/B; B off in tail t0=96)
// x 20 n's. 256 threads = 8 warps, 2 CTAs/SM for phase overlap.
// Warp w: d-slices {(w&1)*64 + lane, +32}, n-range (w>>1)*5 .. +4.
// Shared (94720B/CTA; 2 CTAs = 189440B < 228KB): phiP A/B [K][D] float4 +
// theta A/B [NN][K] float4. Registers: 128/thread cap x 512 thr = 64K RF, fits.
// event_times dtype (int64 vs int32) detected per WARP via ballot on the odd
// int32 words (values <100 -> int64 high words all 0; P(false+ | int32)=1e-64).
// No sync dependency, so the et prefetch issues at cycle ~0 and overlaps the
// tile-load and softmax phases.
//
// Deferred pending a profile: wider n-tiles (RF-pressure risk), split softmax
// kernel (+40MB traffic), cp.async tile loads (~3us).
__global__ __launch_bounds__(256, 2)
void mixture_kernel(const float* __restrict__ lambda_,
                    const int*   __restrict__ ev32,   // raw words of event_times
                    const float* __restrict__ phiP,
                    float* __restrict__ pi,
                    float* __restrict__ theta_out) {
    extern __shared__ float sh[];
    float* phiA_sh = sh;                           // 20*128*4 floats
    float* phiB_sh = phiA_sh + K_ * D_ * 4;
    float* thA_sh  = phiB_sh + K_ * D_ * 4;        // 20*20*4 floats
    float* thB_sh  = thA_sh + NN_ * K_ * 4;

    const int t0   = blockIdx.x * 8;
    const int n0   = blockIdx.y * NN_;
    const int tid  = threadIdx.x;
    const int w    = tid >> 5;
    const int lane = tid & 31;
    const bool has2 = (t0 + 4 < T_);               // tail block: chunk B off

    // ---- per-warp dtype detect (no sync needed) ----
    int probe = ev32[2 * lane + 1];                // odd words 1..63
    unsigned anyv = __ballot_sync(0xffffffffu, probe != 0);
    const int is64 = (anyv == 0) ? 1 : 0;          // uniform within warp

    // ---- et prefetch at cycle ~0 (overlaps tile load + softmax) ----
    const int d0  = (w & 1) * 64 + lane;           // first d-slice
    const int d1  = d0 + 32;                       // second d-slice
    const int nl0 = (w >> 1) * 5;                  // 4 groups x 5 = 20 n
    int etA[5], etB[5];
#pragma unroll
    for (int j = 0; j < 5; j++) {
        size_t iA = (size_t)(n0 + nl0 + j) * D_ + d0;
        size_t iB = (size_t)(n0 + nl0 + j) * D_ + d1;
        etA[j] = ev32[iA << is64];                 // low word == value (vals < 100)
        etB[j] = ev32[iB << is64];
    }

    // ---- cooperative load of phiP tiles: 2x2560 float4, A/B paired for MLP ----
#pragma unroll
    for (int i = 0; i < 10; i++) {
        int idx = tid + i * 256;                   // 0..2559
        int k = idx >> 7;
        int d = idx & 127;
        const float* src = phiP + (k * D_ + d) * T_ + t0;
        float4 vA = *(const float4*)src;
        if (has2) {
            float4 vB = *(const float4*)(src + 4); // same 128B line, batched issue
            ((float4*)phiA_sh)[k * D_ + d] = vA;
            ((float4*)phiB_sh)[k * D_ + d] = vB;
        } else {
            ((float4*)phiA_sh)[k * D_ + d] = vA;
        }
    }

    // ---- softmax over K for (20 n) x (8 t): 160 tasks ----
    // t0 % 8 == 0 -> the 8 loads of one (n,k) row share one 32B-aligned sector.
    if (tid < NN_ * 8) {
        int nl = tid >> 3;
        int tl = tid & 7;
        if (tl < 4 || has2) {
            const float* lp = lambda_ + ((size_t)(n0 + nl) * K_) * T_ + t0 + tl;
            float e[K_];
            float s = 0.0f;
#pragma unroll
            for (int k = 0; k < K_; k++) {
                e[k] = fexp(lp[k * T_]);
                s += e[k];
            }
            float inv = 1.0f / s;
            float* dst = (tl < 4 ? thA_sh : thB_sh) + (tl & 3);
#pragma unroll
            for (int k = 0; k < K_; k++)
                dst[(nl * K_ + k) * 4] = e[k] * inv;
        }
    }
    __syncthreads();

    // ---- write theta tiles to global (both halves of each 32B sector) ----
#pragma unroll
    for (int rep = 0; rep < 2; rep++) {
        int i = tid + rep * 256;                   // 0..399
        if (i < NN_ * K_) {
            int nl = i / K_;
            int k  = i % K_;
            float* dst = theta_out + ((size_t)(n0 + nl) * K_ + k) * T_ + t0;
            *(float4*)dst = ((float4*)thA_sh)[i];
            if (has2)
                *(float4*)(dst + 4) = ((float4*)thB_sh)[i];
        }
    }

    const float hi = 1.0f - EPSV;

    // ---- main register-tiled mixture: 2 d-slices x 5 n per warp ----
#pragma unroll
    for (int c = 0; c < 2; c++) {
        if (c == 1 && !has2) break;
        const float* phic = (c == 0) ? phiA_sh : phiB_sh;
        const float* thc  = (c == 0) ? thA_sh  : thB_sh;
        const int tc = t0 + c * 4;

        unsigned long long aA0[5], aA1[5], aB0[5], aB1[5];
#pragma unroll
        for (int j = 0; j < 5; j++) { aA0[j]=0ull; aA1[j]=0ull; aB0[j]=0ull; aB1[j]=0ull; }

        const ulonglong2* thv = (const ulonglong2*)thc;
        const ulonglong2* pv  = (const ulonglong2*)phic;

#pragma unroll
        for (int k = 0; k < K_; k++) {
            ulonglong2 pA = pv[k * D_ + d0];       // lane-distinct, conflict-free LDS.128
            ulonglong2 pB = pv[k * D_ + d1];
#pragma unroll
            for (int j = 0; j < 5; j++) {
                ulonglong2 th = thv[(nl0 + j) * K_ + k];   // warp-broadcast LDS.128
                asm("fma.rn.f32x2 %0, %1, %2, %0;" : "+l"(aA0[j]) : "l"(th.x), "l"(pA.x));
                asm("fma.rn.f32x2 %0, %1, %2, %0;" : "+l"(aA1[j]) : "l"(th.y), "l"(pA.y));
                asm("fma.rn.f32x2 %0, %1, %2, %0;" : "+l"(aB0[j]) : "l"(th.x), "l"(pB.x));
                asm("fma.rn.f32x2 %0, %1, %2, %0;" : "+l"(aB1[j]) : "l"(th.y), "l"(pB.y));
            }
        }

        // ---- mask + clip + store ----
#pragma unroll
        for (int j = 0; j < 5; j++) {
            float x0, x1, x2, x3;
            int e; float4 r;

            asm("mov.b64 {%0,%1}, %2;" : "=f"(x0), "=f"(x1) : "l"(aA0[j]));
            asm("mov.b64 {%0,%1}, %2;" : "=f"(x2), "=f"(x3) : "l"(aA1[j]));
            e = etA[j];
            r.x = (tc + 0 <= e) ? fminf(fmaxf(x0, EPSV), hi) : EPSV;
            r.y = (tc + 1 <= e) ? fminf(fmaxf(x1, EPSV), hi) : EPSV;
            r.z = (tc + 2 <= e) ? fminf(fmaxf(x2, EPSV), hi) : EPSV;
            r.w = (tc + 3 <= e) ? fminf(fmaxf(x3, EPSV), hi) : EPSV;
            *(float4*)(pi + ((size_t)(n0 + nl0 + j) * D_ + d0) * T_ + tc) = r;

            asm("mov.b64 {%0,%1}, %2;" : "=f"(x0), "=f"(x1) : "l"(aB0[j]));
            asm("mov.b64 {%0,%1}, %2;" : "=f"(x2), "=f"(x3) : "l"(aB1[j]));
            e = etB[j];
            r.x = (tc + 0 <= e) ? fminf(fmaxf(x0, EPSV), hi) : EPSV;
            r.y = (tc + 1 <= e) ? fminf(fmaxf(x1, EPSV), hi) : EPSV;
            r.z = (tc + 2 <= e) ? fminf(fmaxf(x2, EPSV), hi) : EPSV;
            r.w = (tc + 3 <= e) ? fminf(fmaxf(x3, EPSV), hi) : EPSV;
            *(float4*)(pi + ((size_t)(n0 + nl0 + j) * D_ + d1) * T_ + tc) = r;
        }
    }
}

extern "C" void kernel_launch(void* const* d_in, const int* in_sizes, int n_in,
                              void* d_out, int out_size) {
    const float* lambda_ = (const float*)d_in[0];   // [N,K,T] f32
    const float* phi     = (const float*)d_in[1];   // [K,D,T] f32
    const int*   ev32    = (const int*)d_in[2];     // [N,D] int32 OR int64 (detected)

    float* out    = (float*)d_out;
    float* pi     = out + PI_OFF;
    float* theta  = out + THETA_OFF;
    float* phiP   = out + PHIP_OFF;

    const int smem = 2 * (K_ * D_ * 4 + NN_ * K_ * 4) * (int)sizeof(float); // 94720
    cudaFuncSetAttribute(mixture_kernel,
                         cudaFuncAttributeMaxDynamicSharedMemorySize, smem);

    // K1: phi_prob = sigmoid(phi): 256000 elems = 64000 float4
    phi_sigmoid_kernel<<<250, 256>>>(phi, phiP);

    // K2: fused softmax + mixture. grid: x = t8 windows (13, last = 4t tail),
    // y = n-tiles (250)
    dim3 grid((T_ + 7) / 8, N_ / NN_);
    mixture_kernel<<<grid, 256, smem>>>(lambda_, ev32, phiP, pi, theta);
}